// round 9
// baseline (speedup 1.0000x reference)
#include <cuda_runtime.h>
#include <math.h>

#define NF 101
#define UNITS 125
#define G3 375
#define OUT 202
#define KSZ (UNITS*OUT)
#define NW (KSZ+OUT)
#define TT 70
#define STEPS1 56
#define GAMMA 28
#define BATCH 4096
#define CCONST 0.54132485f

// fused operand layout: v = [x(112 pad) | h(128 pad)]
#define KX 112
#define KH 128
#define KV 240
#define WROW 384          // 3 gates * 128 padded units (floats)
#define DROW 256          // padded dense output row (floats)
#define TK 16             // k-rows per tile
#define NT_GRU 15         // 240/16
#define NT_DEN 8          // 128/16

#define OFF_GW 0
#define SZ_GW (KV*WROW)
#define OFF_B0 (OFF_GW+SZ_GW)
#define OFF_B1 (OFF_B0+WROW)
#define OFF_KP (OFF_B1+WROW)
#define SZ_KP (GAMMA*KH*DROW)
#define OFF_BIAS (OFF_KP+SZ_KP)
#define SZ_BIAS (GAMMA*DROW)
#define SCRATCH_TOTAL (OFF_BIAS+SZ_BIAS)

__device__ __align__(16) float g_scratch[SCRATCH_TOTAL];

typedef unsigned long long u64;

// ---- packed f32x2 helpers (sm_103a) ----
__device__ __forceinline__ void fma2(u64& d, u64 a, u64 b){
    asm("fma.rn.f32x2 %0, %1, %2, %0;" : "+l"(d) : "l"(a), "l"(b));
}
__device__ __forceinline__ u64 pack2(float x, float y){
    u64 r; asm("mov.b64 %0, {%1,%2};" : "=l"(r) : "f"(x), "f"(y)); return r;
}
__device__ __forceinline__ float2 unpack2(u64 v){
    float2 r; asm("mov.b64 {%0,%1}, %2;" : "=f"(r.x), "=f"(r.y) : "l"(v)); return r;
}

// ---- cp.async helpers ----
__device__ __forceinline__ void cpa16(void* s, const void* g){
    unsigned ss = (unsigned)__cvta_generic_to_shared(s);
    asm volatile("cp.async.cg.shared.global [%0], [%1], 16;" :: "r"(ss), "l"(g));
}
__device__ __forceinline__ void cp_commit(){ asm volatile("cp.async.commit_group;"); }
__device__ __forceinline__ void cp_wait1(){ asm volatile("cp.async.wait_group 1;" ::: "memory"); }

// ---- math ----
__device__ __forceinline__ float sp(float x){
    float r = log1pf(__expf(x));
    return (x > 15.f) ? x : r;
}
__device__ __forceinline__ float sigm(float x){
    return __fdividef(1.f, 1.f + __expf(-x));
}
__device__ __forceinline__ float mytanh(float x){
    return __fdividef(2.f, 1.f + __expf(-2.f*x)) - 1.f;
}

// ---- weight prep ----
__device__ __forceinline__ float dvw(int s, int w,
    const float* dv_loc, const float* dv_rho, const float* eps_w0, const float* eps_w)
{
    float sd = 1e-5f + 0.01f * sp(CCONST + dv_rho[w]);
    float e  = (s == 0) ? eps_w0[w] : eps_w[(size_t)(s-1)*NW + w];
    return dv_loc[w] + sd * e;
}

__global__ void prep_kernel(const float* __restrict__ W_k, const float* __restrict__ U,
                            const float* __restrict__ b,   const float* __restrict__ dv_loc,
                            const float* __restrict__ dv_rho, const float* __restrict__ eps_w0,
                            const float* __restrict__ eps_w)
{
    for (int i = blockIdx.x*blockDim.x + threadIdx.x; i < SCRATCH_TOTAL; i += gridDim.x*blockDim.x){
        float v = 0.f;
        if (i < OFF_B0){
            int k = i / WROW, c = i % WROW;
            int g = c / 128, u = c % 128;
            if (u < UNITS){
                if (k < NF)                     v = W_k[k*G3 + g*UNITS + u];
                else if (k >= KX && k < KX+UNITS) v = U[(k-KX)*G3 + g*UNITS + u];
            }
        } else if (i < OFF_B1){
            int c = i - OFF_B0; int g = c / 128, u = c % 128;
            if (u < UNITS) v = b[g*UNITS + u];
        } else if (i < OFF_KP){
            int c = i - OFF_B1; int g = c / 128, u = c % 128;
            if (u < UNITS) v = b[G3 + g*UNITS + u];
        } else if (i < OFF_BIAS){
            int idx = i - OFF_KP; int s = idx / (KH*DROW);
            int rem = idx % (KH*DROW); int u = rem / DROW, o = rem % DROW;
            if (u < UNITS && o < OUT) v = dvw(s, u*OUT + o, dv_loc, dv_rho, eps_w0, eps_w);
        } else {
            int idx = i - OFF_BIAS; int s = idx / DROW, o = idx % DROW;
            if (o < OUT) v = dvw(s, KSZ + o, dv_loc, dv_rho, eps_w0, eps_w);
        }
        g_scratch[i] = v;
    }
}

// ---- main kernel geometry ----
#define ROWS_CTA 16
#define VS 241            // u64 stride per row of v (odd: avoids bank conflicts)
#define YS 208            // float stride per row of y
#define WBUF_U64 3072     // 24KB GRU tile in u64
#define DBUF_U64 2048     // 16KB dense tile in u64

#define SMEM_V_BYTES (ROWS_CTA*VS*8)                 // 30848
#define SMEM_Y_BYTES (ROWS_CTA*YS*4)                 // 13312
#define SMEM_W_BYTES (2*WBUF_U64*8)                  // 49152
#define SMEM_BYTES (SMEM_V_BYTES + SMEM_Y_BYTES + SMEM_W_BYTES)

__device__ __forceinline__ void gru_tiles(int t0, int t1, u64 (&acc)[3][4],
    const u64* __restrict__ sh_v, u64* __restrict__ sh_w,
    int p, int r0, int tid)
{
    const char* gw = (const char*)(g_scratch + OFF_GW);
    for (int t = t0; t < t1; ++t){
        if (t + 1 < NT_GRU){
            const char* src = gw + (size_t)(t+1)*TK*WROW*4;
            char* d = (char*)(sh_w + ((t+1)&1)*WBUF_U64);
            #pragma unroll
            for (int c = 0; c < 6; ++c)
                cpa16(d + c*4096 + tid*16, src + c*4096 + tid*16);
        }
        cp_commit();
        cp_wait1();
        __syncthreads();
        const u64* wt = sh_w + (t&1)*WBUF_U64 + p;
        const u64* vb = sh_v + (size_t)r0*VS + t*TK;
        #pragma unroll
        for (int kl = 0; kl < TK; ++kl){
            u64 xv[4];
            #pragma unroll
            for (int r = 0; r < 4; ++r) xv[r] = vb[r*VS + kl];
            #pragma unroll
            for (int g = 0; g < 3; ++g){
                u64 w = wt[kl*192 + g*64];
                #pragma unroll
                for (int r = 0; r < 4; ++r) fma2(acc[g][r], w, xv[r]);
            }
        }
        __syncthreads();
    }
}

__device__ __forceinline__ void gru_step(u64* __restrict__ sh_v, u64* __restrict__ sh_w,
                                         int warp, int lane, int tid)
{
    const int p  = warp*8 + (lane & 7);      // unit-pair column 0..63
    const int r0 = (lane >> 3) * 4;          // 0,4,8,12
    u64 amx[3][4], ami[3][4];
    const u64* b0 = (const u64*)(g_scratch + OFF_B0);
    const u64* b1 = (const u64*)(g_scratch + OFF_B1);
    #pragma unroll
    for (int g = 0; g < 3; ++g){
        u64 v0 = b0[g*64 + p], v1 = b1[g*64 + p];
        #pragma unroll
        for (int r = 0; r < 4; ++r){ amx[g][r] = v0; ami[g][r] = v1; }
    }

    // prolog: prefetch tile 0 into buffer 0
    {
        const char* src = (const char*)(g_scratch + OFF_GW);
        char* d = (char*)sh_w;
        #pragma unroll
        for (int c = 0; c < 6; ++c)
            cpa16(d + c*4096 + tid*16, src + c*4096 + tid*16);
        cp_commit();
    }
    gru_tiles(0, 7,       amx, sh_v, sh_w, p, r0, tid);   // x part (k 0..111)
    gru_tiles(7, NT_GRU,  ami, sh_v, sh_w, p, r0, tid);   // h part (k 112..239)

    // gate nonlinearity + h update (own columns only)
    u64* hp = sh_v + (size_t)r0*VS + KX;
    #pragma unroll
    for (int r = 0; r < 4; ++r){
        float2 xz = unpack2(amx[0][r]), rz = unpack2(ami[0][r]);
        float2 xr = unpack2(amx[1][r]), rr = unpack2(ami[1][r]);
        float2 xh = unpack2(amx[2][r]), rh = unpack2(ami[2][r]);
        float h_old0 = unpack2(hp[r*VS + 2*p]).x;
        float h_old1 = unpack2(hp[r*VS + 2*p + 1]).x;
        float z0 = sigm(xz.x + rz.x), z1 = sigm(xz.y + rz.y);
        float g0 = sigm(xr.x + rr.x), g1 = sigm(xr.y + rr.y);
        float c0 = mytanh(xh.x + g0*rh.x), c1 = mytanh(xh.y + g1*rh.y);
        float h0 = z0*h_old0 + (1.f - z0)*c0;
        float h1 = z1*h_old1 + (1.f - z1)*c1;
        hp[r*VS + 2*p]     = pack2(h0, h0);
        hp[r*VS + 2*p + 1] = pack2(h1, h1);
    }
    __syncthreads();
}

__device__ __forceinline__ void dense_step(int s, const u64* __restrict__ sh_v,
                                           u64* __restrict__ sh_w, float* __restrict__ sh_y,
                                           int warp, int lane, int tid)
{
    const int c  = warp*8 + (lane & 7);      // col-pair unit 0..63 (covers 4 float outputs)
    const int r0 = (lane >> 3) * 4;
    const char* kw = (const char*)(g_scratch + OFF_KP + (size_t)s*(KH*DROW));
    u64 acc[2][4];
    {
        const u64* bias = (const u64*)(g_scratch + OFF_BIAS) + s*128;
        u64 bx = bias[2*c], by = bias[2*c + 1];
        #pragma unroll
        for (int r = 0; r < 4; ++r){ acc[0][r] = bx; acc[1][r] = by; }
    }
    // prolog
    {
        char* d = (char*)sh_w;
        #pragma unroll
        for (int ch = 0; ch < 4; ++ch)
            cpa16(d + ch*4096 + tid*16, kw + ch*4096 + tid*16);
        cp_commit();
    }
    for (int t = 0; t < NT_DEN; ++t){
        if (t + 1 < NT_DEN){
            const char* src = kw + (size_t)(t+1)*TK*DROW*4;
            char* d = (char*)(sh_w + ((t+1)&1)*DBUF_U64);
            #pragma unroll
            for (int ch = 0; ch < 4; ++ch)
                cpa16(d + ch*4096 + tid*16, src + ch*4096 + tid*16);
        }
        cp_commit();
        cp_wait1();
        __syncthreads();
        const u64* wt = sh_w + (t&1)*DBUF_U64;
        const u64* hb = sh_v + (size_t)r0*VS + KX + t*TK;
        #pragma unroll
        for (int kl = 0; kl < TK; ++kl){
            u64 hv[4];
            #pragma unroll
            for (int r = 0; r < 4; ++r) hv[r] = hb[r*VS + kl];
            ulonglong2 w = *(const ulonglong2*)(wt + kl*128 + 2*c);
            #pragma unroll
            for (int r = 0; r < 4; ++r){
                fma2(acc[0][r], w.x, hv[r]);
                fma2(acc[1][r], w.y, hv[r]);
            }
        }
        __syncthreads();
    }
    const int o = 4*c;
    #pragma unroll
    for (int r = 0; r < 4; ++r){
        float2 a = unpack2(acc[0][r]);
        float2 d2 = unpack2(acc[1][r]);
        float* yr = sh_y + (size_t)(r0 + r)*YS;
        if (o     < OUT) yr[o]     = a.x;
        if (o + 1 < OUT) yr[o + 1] = a.y;
        if (o + 2 < OUT) yr[o + 2] = d2.x;
        if (o + 3 < OUT) yr[o + 3] = d2.y;
    }
    __syncthreads();
}

__global__ void __launch_bounds__(256, 2)
rnn_kernel(const float* __restrict__ inputs, const float* __restrict__ eps_s,
           float* __restrict__ out)
{
    extern __shared__ unsigned char smem[];
    u64*   sh_v = (u64*)smem;
    float* sh_y = (float*)(smem + SMEM_V_BYTES);
    u64*   sh_w = (u64*)(smem + SMEM_V_BYTES + SMEM_Y_BYTES);

    const int tid  = threadIdx.x;
    const int lane = tid & 31;
    const int warp = tid >> 5;
    const int row0 = blockIdx.x * ROWS_CTA;

    // zero v (x-pad stays 0 forever; h starts 0; h-pad cols stay 0 by construction)
    for (int i = tid; i < ROWS_CTA*VS; i += 256) sh_v[i] = 0ULL;
    __syncthreads();

    // phase 1: teacher-forced GRU (56 steps)
    for (int t = 0; t < STEPS1; ++t){
        for (int i = tid; i < ROWS_CTA*NF; i += 256){
            int r = i / NF, k = i - r*NF;
            float v = inputs[((size_t)(row0 + r)*TT + t)*NF + k];
            sh_v[r*VS + k] = pack2(v, v);
        }
        __syncthreads();
        gru_step(sh_v, sh_w, warp, lane, tid);
    }

    // y0 + feedback loop
    for (int s = 0; s < GAMMA; ++s){
        if (s > 0){
            for (int i = tid; i < ROWS_CTA*NF; i += 256){
                int r = i / NF, k = i - r*NF;
                float loc = sh_y[r*YS + k];
                float sc  = 1e-5f + 0.05f*sp(CCONST + sh_y[r*YS + NF + k]);
                float xv  = loc + sc * eps_s[((size_t)(s-1)*BATCH + row0 + r)*NF + k];
                sh_v[r*VS + k] = pack2(xv, xv);
            }
            __syncthreads();
            gru_step(sh_v, sh_w, warp, lane, tid);
        }
        dense_step(s, sh_v, sh_w, sh_y, warp, lane, tid);
        // emit: loc passthrough, scale transform
        for (int i = tid; i < ROWS_CTA*OUT; i += 256){
            int r = i / OUT, o = i - r*OUT;
            float v = sh_y[r*YS + o];
            if (o >= NF) v = 1e-5f + 0.05f*sp(CCONST + v);
            out[((size_t)(row0 + r)*GAMMA + s)*OUT + o] = v;
        }
    }
}

extern "C" void kernel_launch(void* const* d_in, const int* in_sizes, int n_in,
                              void* d_out, int out_size)
{
    const float* inputs = (const float*)d_in[0];
    const float* W_k    = (const float*)d_in[1];
    const float* U      = (const float*)d_in[2];
    const float* b      = (const float*)d_in[3];
    const float* dv_loc = (const float*)d_in[4];
    const float* dv_rho = (const float*)d_in[5];
    const float* eps_w0 = (const float*)d_in[6];
    const float* eps_w  = (const float*)d_in[7];
    const float* eps_s  = (const float*)d_in[8];
    float* out = (float*)d_out;

    (void)in_sizes; (void)n_in; (void)out_size;

    cudaFuncSetAttribute(rnn_kernel, cudaFuncAttributeMaxDynamicSharedMemorySize, SMEM_BYTES);

    prep_kernel<<<1024, 256>>>(W_k, U, b, dv_loc, dv_rho, eps_w0, eps_w);
    rnn_kernel<<<BATCH/ROWS_CTA, 256, SMEM_BYTES>>>(inputs, eps_s, out);
}